// round 14
// baseline (speedup 1.0000x reference)
#include <cuda_runtime.h>
#include <cuda_fp16.h>
#include <cstdint>
#include <math.h>

// Problem constants
#define B_   128
#define C_   1024
#define R_   256
#define T_   4
#define H_   7
#define W_   7
#define P_   196     // T*H*W
#define EPSV 1e-5f

// ---------------- intermediates (device globals; no allocation allowed) ----
__device__ float  g_hmean[B_ * R_];
__device__ __half g_xh[(size_t)B_ * P_ * C_];   // x transposed: [b][p][c] fp16
__device__ __half g_w1h[R_ * C_];               // w1 fp16: [r][c]

// ---------------- helpers ---------------------------------------------------
__device__ __forceinline__ void mma_f16(float& d0, float& d1, float& d2, float& d3,
                                        uint32_t a0, uint32_t a1, uint32_t a2, uint32_t a3,
                                        uint32_t b0, uint32_t b1) {
    asm volatile(
        "mma.sync.aligned.m16n8k16.row.col.f32.f16.f16.f32 "
        "{%0,%1,%2,%3}, {%4,%5,%6,%7}, {%8,%9}, {%0,%1,%2,%3};\n"
        : "+f"(d0), "+f"(d1), "+f"(d2), "+f"(d3)
        : "r"(a0), "r"(a1), "r"(a2), "r"(a3), "r"(b0), "r"(b1));
}

__device__ __forceinline__ void ldsm_x4(uint32_t& r0, uint32_t& r1, uint32_t& r2,
                                        uint32_t& r3, uint32_t addr) {
    asm volatile("ldmatrix.sync.aligned.m8n8.x4.shared.b16 {%0,%1,%2,%3}, [%4];"
                 : "=r"(r0), "=r"(r1), "=r"(r2), "=r"(r3) : "r"(addr));
}
__device__ __forceinline__ void ldsm_x2(uint32_t& r0, uint32_t& r1, uint32_t addr) {
    asm volatile("ldmatrix.sync.aligned.m8n8.x2.shared.b16 {%0,%1}, [%2];"
                 : "=r"(r0), "=r"(r1) : "r"(addr));
}

__device__ __forceinline__ void cp16(void* smem_dst, const void* gsrc, int srcbytes) {
    uint32_t s = (uint32_t)__cvta_generic_to_shared(smem_dst);
    asm volatile("cp.async.ca.shared.global [%0], [%1], 16, %2;\n"
                 :: "r"(s), "l"(gsrc), "r"(srcbytes));
}
__device__ __forceinline__ void cp_commit() { asm volatile("cp.async.commit_group;\n"); }
__device__ __forceinline__ void cp_wait0()  { asm volatile("cp.async.wait_group 0;\n"); }
__device__ __forceinline__ void cp_wait1()  { asm volatile("cp.async.wait_group 1;\n"); }

// ============================================================================
// Kernel P: blockIdx.x < 16 : transpose+convert x[b][c][p] f32 -> g_xh[b][p][c]
//           blockIdx.x ==16 : convert w1 -> g_w1h (2 rows per blockIdx.y)
// ============================================================================
__global__ void __launch_bounds__(256)
kernelP(const float* __restrict__ x, const float* __restrict__ w1) {
    const int tid = threadIdx.x;
    const int b   = blockIdx.y;

    if (blockIdx.x == 16) {   // w1 convert: rows [2b, 2b+2)
        const int e0 = b * 2048;
        #pragma unroll
        for (int it = 0; it < 2; it++) {
            int idx = it * 256 + tid;
            float4 v = reinterpret_cast<const float4*>(w1 + e0)[idx];
            __half2 h0 = __floats2half2_rn(v.x, v.y);
            __half2 h1 = __floats2half2_rn(v.z, v.w);
            uint2 u;
            u.x = *reinterpret_cast<uint32_t*>(&h0);
            u.y = *reinterpret_cast<uint32_t*>(&h1);
            reinterpret_cast<uint2*>(g_w1h + e0)[idx] = u;
        }
        return;
    }

    __shared__ unsigned short xs[64 * 202];
    const int c0 = blockIdx.x * 64;

    for (int idx = tid; idx < 64 * 49; idx += 256) {
        int c = idx / 49, q = idx - c * 49;
        float4 v = reinterpret_cast<const float4*>(
                       x + ((size_t)b * C_ + c0 + c) * P_)[q];
        unsigned short* dst = xs + c * 202 + q * 4;
        dst[0] = __half_as_ushort(__float2half_rn(v.x));
        dst[1] = __half_as_ushort(__float2half_rn(v.y));
        dst[2] = __half_as_ushort(__float2half_rn(v.z));
        dst[3] = __half_as_ushort(__float2half_rn(v.w));
    }
    __syncthreads();

    // write x_h[b][p][c0..c0+63]: uint4 per thread = 8 consecutive c
    uint4* outu4 = reinterpret_cast<uint4*>(g_xh);
    for (int idx = tid; idx < P_ * 8; idx += 256) {
        int p = idx >> 3, ch = idx & 7;                  // ch = c-octet
        const unsigned short* s0 = xs + (8 * ch) * 202 + p;
        uint4 u;
        u.x = (uint32_t)s0[0 * 202] | ((uint32_t)s0[1 * 202] << 16);
        u.y = (uint32_t)s0[2 * 202] | ((uint32_t)s0[3 * 202] << 16);
        u.z = (uint32_t)s0[4 * 202] | ((uint32_t)s0[5 * 202] << 16);
        u.w = (uint32_t)s0[6 * 202] | ((uint32_t)s0[7 * 202] << 16);
        outu4[((size_t)b * P_ + p) * (C_ / 8) + (c0 >> 3) + ch] = u;
    }
}

// ============================================================================
// Kernel A: GEMM  H[r,p] = sum_c w1[r,c] * x[b,c,p]   (fp16 HMMA m16n8k16)
// fused BN-affine + hardswish + mean over p  ->  g_hmean[b][r]
// CTA = (mhalf, batch): 128 r rows x 196 p.
// 8 warps split along M ONLY (m16 tiles); each warp spans full N.
// N passes: 13 n8 (cols 0..103) then 12 n8 (cols 104..199, masked >=196).
// All warps do identical work -> balanced behind the per-chunk barrier.
// KC=64, 3-stage cp.async, ldmatrix frags (144B pitch, conflict-free).
// ============================================================================
#define KC      64
#define NKC     16     // 1024/64
#define PITCH   144    // row pitch bytes (36 words: LDSM phases cover all banks)
#define ASZ     18432  // 128 rows * 144 B
#define BSZ     14976  // 104 rows * 144 B (pass0 max)

// smem byte offsets
#define OFF_A    0
#define OFF_B    (3 * ASZ)                   // 55296
#define OFF_PART (OFF_B + 3 * BSZ)           // 100224 (256 f32)
#define OFF_SC   (OFF_PART + 1024)           // 101248 (128 f32)
#define OFF_BI   (OFF_SC + 512)              // 101760 (128 f32)
#define SMEM_A_TOTAL (OFF_BI + 512)          // 102272 B

// one K=64 chunk for a warp with NT n8-tiles (full N span)
template<int NT>
__device__ __forceinline__ void mma_chunk(
    uint32_t abase, uint32_t bbase, float d[13][4],
    uint32_t a_row, uint32_t a_coff,
    uint32_t rb4, uint32_t b_coff4, uint32_t rb2, uint32_t b_coff2) {
    #pragma unroll
    for (int kk = 0; kk < 4; kk++) {
        const uint32_t kb = (uint32_t)(kk * 32);

        uint32_t a0, a1, a2, a3;
        ldsm_x4(a0, a1, a2, a3, abase + a_row * PITCH + kb + a_coff);

        uint32_t bb[13][2];
        #pragma unroll
        for (int ntp = 0; ntp < NT / 2; ntp++)
            ldsm_x4(bb[2 * ntp][0], bb[2 * ntp][1],
                    bb[2 * ntp + 1][0], bb[2 * ntp + 1][1],
                    bbase + (rb4 + ntp * 16) * PITCH + kb + b_coff4);
        if constexpr (NT & 1)
            ldsm_x2(bb[NT - 1][0], bb[NT - 1][1],
                    bbase + (rb2 + (NT / 2) * 16) * PITCH + kb + b_coff2);

        #pragma unroll
        for (int nt = 0; nt < NT; nt++)
            mma_f16(d[nt][0], d[nt][1], d[nt][2], d[nt][3],
                    a0, a1, a2, a3, bb[nt][0], bb[nt][1]);
    }
}

__global__ void __launch_bounds__(256, 2)
kernelA(const float* __restrict__ g1, const float* __restrict__ b1,
        const float* __restrict__ m1, const float* __restrict__ v1) {
    extern __shared__ __align__(16) char smem[];
    float* part = reinterpret_cast<float*>(smem + OFF_PART);
    float* sc   = reinterpret_cast<float*>(smem + OFF_SC);
    float* bi   = reinterpret_cast<float*>(smem + OFF_BI);
    const uint32_t sbase = (uint32_t)__cvta_generic_to_shared(smem);

    const int mh   = blockIdx.x;
    const int b    = blockIdx.y;
    const int tid  = threadIdx.x;
    const int lane = tid & 31;
    const int warp = tid >> 5;     // 0..7 : m16 tile index
    const int rbase = mh * 128;

    if (tid < 256) { }             // (shape doc)
    if (tid < 128) {
        part[tid]       = 0.f;
        part[tid + 128] = 0.f;
        int r = rbase + tid;
        float s = g1[r] * rsqrtf(v1[r] + EPSV);
        sc[tid] = s;
        bi[tid] = b1[r] - m1[r] * s;
    }

    const __half* w1h = g_w1h;
    const __half* xh  = g_xh + (size_t)b * P_ * C_;

    // ldmatrix lane-static address components
    const uint32_t a_row  = (uint32_t)(warp * 16 + (lane & 15));
    const uint32_t a_coff = (uint32_t)((lane >> 4) << 4);
    const int      m4     = lane >> 3;
    const uint32_t rb4    = (uint32_t)(((m4 >> 1) << 3) + (lane & 7));
    const uint32_t b_coff4= (uint32_t)((m4 & 1) << 4);
    const uint32_t rb2    = (uint32_t)(lane & 7);
    const uint32_t b_coff2= (uint32_t)(((lane >> 3) & 1) << 4);

    #pragma unroll 1
    for (int np = 0; np < 2; np++) {
        __syncthreads();

        const int NTp   = (np == 0) ? 13 : 12;
        const int pcol0 = np * 104;
        const int blim  = NTp * 64;          // staged rows * 8 (832 / 768)

        auto stageA = [&](int s, int kc) {
            char* base = smem + OFF_A + s * ASZ;
            #pragma unroll
            for (int it = 0; it < 4; it++) {       // 1024 cp16
                int idx = it * 256 + tid;
                int row = idx >> 3, ch = idx & 7;
                cp16(base + row * PITCH + ch * 16,
                     w1h + (size_t)(rbase + row) * C_ + kc + ch * 8, 16);
            }
        };
        auto stageB = [&](int s, int kc) {
            char* base = smem + OFF_B + s * BSZ;
            #pragma unroll
            for (int it = 0; it < 4; it++) {
                int idx = it * 256 + tid;
                if (idx < blim) {
                    int row = idx >> 3, ch = idx & 7;
                    int p = pcol0 + row;
                    int ok = (p < P_);
                    const __half* src = xh + (size_t)(ok ? p : 0) * C_ + kc + ch * 8;
                    cp16(base + row * PITCH + ch * 16, src, ok ? 16 : 0);
                }
            }
        };

        stageA(0, 0);  stageB(0, 0);  cp_commit();
        stageA(1, KC); stageB(1, KC); cp_commit();

        float d[13][4];
        #pragma unroll
        for (int nt = 0; nt < 13; nt++)
            #pragma unroll
            for (int j = 0; j < 4; j++) d[nt][j] = 0.f;

        #pragma unroll 1
        for (int kci = 0; kci < NKC; kci++) {
            if (kci + 1 < NKC) cp_wait1(); else cp_wait0();
            __syncthreads();

            if (kci + 2 < NKC) {
                int nb = (kci + 2) % 3;
                stageA(nb, (kci + 2) * KC);
                stageB(nb, (kci + 2) * KC);
                cp_commit();
            }

            const uint32_t abase = sbase + OFF_A + (kci % 3) * ASZ;
            const uint32_t bbase = sbase + OFF_B + (kci % 3) * BSZ;

            if (np == 0)
                mma_chunk<13>(abase, bbase, d, a_row, a_coff, rb4, b_coff4, rb2, b_coff2);
            else
                mma_chunk<12>(abase, bbase, d, a_row, a_coff, rb4, b_coff4, rb2, b_coff2);
        }

        // epilogue: BN affine + hardswish + per-row partial sums
        const int pbase = pcol0 + (lane & 3) * 2;
        const int rl0 = warp * 16 + (lane >> 2);
        const int rl1 = rl0 + 8;
        const float s0c = sc[rl0], b0c = bi[rl0];
        const float s1c = sc[rl1], b1c = bi[rl1];
        float acc0 = 0.f, acc1 = 0.f;
        #pragma unroll
        for (int nt = 0; nt < 13; nt++) {
            #pragma unroll
            for (int jj = 0; jj < 2; jj++) {
                int p = pbase + nt * 8 + jj;
                if (nt < NTp && p < P_) {
                    float h0 = d[nt][jj] * s0c + b0c;
                    acc0 += h0 * fminf(fmaxf(h0 + 3.f, 0.f), 6.f) * (1.f / 6.f);
                    float h1 = d[nt][2 + jj] * s1c + b1c;
                    acc1 += h1 * fminf(fmaxf(h1 + 3.f, 0.f), 6.f) * (1.f / 6.f);
                }
            }
        }
        acc0 += __shfl_xor_sync(0xFFFFFFFFu, acc0, 1);
        acc0 += __shfl_xor_sync(0xFFFFFFFFu, acc0, 2);
        acc1 += __shfl_xor_sync(0xFFFFFFFFu, acc1, 1);
        acc1 += __shfl_xor_sync(0xFFFFFFFFu, acc1, 2);
        if ((lane & 3) == 0) {
            // exclusive writer per (np, row)
            part[np * 128 + rl0] += acc0;
            part[np * 128 + rl1] += acc1;
        }
    }

    __syncthreads();
    if (tid < 128)
        g_hmean[b * R_ + rbase + tid] = (part[tid] + part[128 + tid]) * (1.f / (float)P_);
}

// ============================================================================
// Kernel C: head (logits/sigmoid/coords, recomputed per block) + ROI align 3D.
// Block = (64-ch tile, batch), 256 thr. cp.async tile staging overlaps
// coords + tap-table computation. fp16 obuf.
// ============================================================================
__global__ void __launch_bounds__(256)
kernelC(const float* __restrict__ w2, const float* __restrict__ g2,
        const float* __restrict__ b2, const float* __restrict__ m2,
        const float* __restrict__ v2, float* __restrict__ out) {
    __shared__ __half xs[P_ * 64];       // 25088 B
    __shared__ __half obuf[75 * 66];     // 9900 B
    __shared__ float  w8[75 * 8];        // 2400 B
    __shared__ short  idx8[75 * 8];      // 1200 B
    __shared__ float  csm[6];

    const int tid  = threadIdx.x;
    const int lane = tid & 31;
    const int warp = tid >> 5;
    const int b    = blockIdx.y;
    const int cc   = blockIdx.x * 64;

    const __half* xh = g_xh + (size_t)b * P_ * C_;

    // async tile stage: 1568 cp16 (overlaps with coords/table computation)
    #pragma unroll
    for (int it = 0; it < 7; it++) {
        int i = it * 256 + tid;
        if (i < P_ * 8) {
            int p = i >> 3, q = i & 7;
            cp16(xs + p * 64 + q * 8, xh + (size_t)p * C_ + cc + q * 8, 16);
        }
    }
    cp_commit();

    // inline head: warp j (<6) computes logit j -> coord csm[j]
    if (warp < 6) {
        const float* h = g_hmean + b * R_;
        float s = 0.f;
        #pragma unroll
        for (int r = lane; r < R_; r += 32) s += h[r] * w2[warp * R_ + r];
        #pragma unroll
        for (int off = 16; off; off >>= 1) s += __shfl_xor_sync(0xFFFFFFFFu, s, off);
        if (lane == 0) {
            float sf = g2[warp] * rsqrtf(v2[warp] + EPSV);
            float l  = (s - m2[warp]) * sf + b2[warp];
            float sig = 1.f / (1.f + expf(-l));
            const float SC[3] = {7.f, 7.f, 4.f};
            csm[warp] = (warp < 3) ? (0.5f * sig * SC[warp])
                                   : ((1.f - 0.5f * sig) * SC[warp - 3]);
        }
    }
    __syncthreads();

    if (tid < 75) {
        const int ot = tid / 25, rr = tid % 25;
        const int oy = rr / 5,   ox = rr - oy * 5;

        auto prep = [&](int axis, int i, int n, float size,
                        int& lo, int& hi, float& w0, float& w1) {
            float s = csm[axis], e = csm[3 + axis];
            float bin = (e - s) / (float)n;
            float c = s + ((float)i + 0.5f) * bin;
            float valid = (c >= -1.f && c <= size) ? 1.f : 0.f;
            c = fminf(fmaxf(c, 0.f), size - 1.f);
            lo = (int)floorf(c);
            hi = min(lo + 1, (int)size - 1);
            float f = c - (float)lo;
            w0 = (1.f - f) * valid;
            w1 = f * valid;
        };

        int xl, xh2, yl, yh2, tl, th2;
        float xw0, xw1, yw0, yw1, tw0, tw1;
        prep(0, ox, 5, 7.f, xl, xh2, xw0, xw1);
        prep(1, oy, 5, 7.f, yl, yh2, yw0, yw1);
        prep(2, ot, 3, 4.f, tl, th2, tw0, tw1);

        #pragma unroll
        for (int k = 0; k < 8; k++) {
            int ti = (k & 4) ? th2 : tl;  float tw = (k & 4) ? tw1 : tw0;
            int yi = (k & 2) ? yh2 : yl;  float yw = (k & 2) ? yw1 : yw0;
            int xi = (k & 1) ? xh2 : xl;  float xw = (k & 1) ? xw1 : xw0;
            w8[tid * 8 + k]   = tw * yw * xw;
            idx8[tid * 8 + k] = (short)(ti * 49 + yi * 7 + xi);
        }
    }
    cp_wait0();
    __syncthreads();

    // gather: warp owns o; lane = channel pair. Even/odd taps accumulate
    // into independent registers (halved dependency chain).
    #pragma unroll 1
    for (int o = warp; o < 75; o += 8) {
        float ax0 = 0.f, ay0 = 0.f, ax1 = 0.f, ay1 = 0.f;
        #pragma unroll
        for (int k = 0; k < 8; k += 2) {
            float w0  = w8[o * 8 + k];
            int   id0 = idx8[o * 8 + k];
            float w1  = w8[o * 8 + k + 1];
            int   id1 = idx8[o * 8 + k + 1];
            __half2 h0 = *reinterpret_cast<const __half2*>(xs + id0 * 64 + lane * 2);
            __half2 h1 = *reinterpret_cast<const __half2*>(xs + id1 * 64 + lane * 2);
            float2 f0 = __half22float2(h0);
            float2 f1 = __half22float2(h1);
            ax0 += w0 * f0.x;  ay0 += w0 * f0.y;
            ax1 += w1 * f1.x;  ay1 += w1 * f1.y;
        }
        __half2 hv = __floats2half2_rn(ax0 + ax1, ay0 + ay1);
        *reinterpret_cast<__half2*>(obuf + o * 66 + lane * 2) = hv;
    }
    __syncthreads();

    // write-out: out index linear in i; (c,o) tracked incrementally (no div)
    {
        float* ob = out + ((size_t)(b * C_) + cc) * 75;
        int c = tid / 75;
        int o = tid - c * 75;
        for (int i = tid; i < 64 * 75; i += 256) {
            ob[i] = __half2float(obuf[o * 66 + c]);
            c += 3; o += 31;
            if (o >= 75) { o -= 75; c++; }
        }
    }
}

// ============================================================================
extern "C" void kernel_launch(void* const* d_in, const int* in_sizes, int n_in,
                              void* d_out, int out_size) {
    const float* x  = (const float*)d_in[0];
    const float* w1 = (const float*)d_in[1];
    const float* g1 = (const float*)d_in[2];
    const float* b1 = (const float*)d_in[3];
    const float* m1 = (const float*)d_in[4];
    const float* v1 = (const float*)d_in[5];
    const float* w2 = (const float*)d_in[6];
    const float* g2 = (const float*)d_in[7];
    const float* b2 = (const float*)d_in[8];
    const float* m2 = (const float*)d_in[9];
    const float* v2 = (const float*)d_in[10];
    float* out = (float*)d_out;

    cudaFuncSetAttribute(kernelA, cudaFuncAttributeMaxDynamicSharedMemorySize,
                         (int)SMEM_A_TOTAL);

    dim3 gridP(17, B_);
    kernelP<<<gridP, 256>>>(x, w1);
    dim3 gridA(2, B_);
    kernelA<<<gridA, 256, SMEM_A_TOTAL>>>(g1, b1, m1, v1);
    dim3 gridC(C_ / 64, B_);
    kernelC<<<gridC, 256>>>(w2, g2, b2, m2, v2, out);
}

// round 15
// speedup vs baseline: 1.0566x; 1.0566x over previous
#include <cuda_runtime.h>
#include <cuda_fp16.h>
#include <cstdint>
#include <math.h>

// Problem constants
#define B_   128
#define C_   1024
#define R_   256
#define T_   4
#define H_   7
#define W_   7
#define P_   196     // T*H*W
#define EPSV 1e-5f

// ---------------- intermediates (device globals; no allocation allowed) ----
__device__ float  g_hmean[B_ * R_];
__device__ __half g_xh[(size_t)B_ * P_ * C_];   // x transposed: [b][p][c] fp16
__device__ __half g_w1h[R_ * C_];               // w1 fp16: [r][c]

// ---------------- helpers ---------------------------------------------------
__device__ __forceinline__ void mma_f16(float& d0, float& d1, float& d2, float& d3,
                                        uint32_t a0, uint32_t a1, uint32_t a2, uint32_t a3,
                                        uint32_t b0, uint32_t b1) {
    asm volatile(
        "mma.sync.aligned.m16n8k16.row.col.f32.f16.f16.f32 "
        "{%0,%1,%2,%3}, {%4,%5,%6,%7}, {%8,%9}, {%0,%1,%2,%3};\n"
        : "+f"(d0), "+f"(d1), "+f"(d2), "+f"(d3)
        : "r"(a0), "r"(a1), "r"(a2), "r"(a3), "r"(b0), "r"(b1));
}

__device__ __forceinline__ void ldsm_x4(uint32_t& r0, uint32_t& r1, uint32_t& r2,
                                        uint32_t& r3, uint32_t addr) {
    asm volatile("ldmatrix.sync.aligned.m8n8.x4.shared.b16 {%0,%1,%2,%3}, [%4];"
                 : "=r"(r0), "=r"(r1), "=r"(r2), "=r"(r3) : "r"(addr));
}
__device__ __forceinline__ void ldsm_x2(uint32_t& r0, uint32_t& r1, uint32_t addr) {
    asm volatile("ldmatrix.sync.aligned.m8n8.x2.shared.b16 {%0,%1}, [%2];"
                 : "=r"(r0), "=r"(r1) : "r"(addr));
}

__device__ __forceinline__ void cp16(void* smem_dst, const void* gsrc, int srcbytes) {
    uint32_t s = (uint32_t)__cvta_generic_to_shared(smem_dst);
    asm volatile("cp.async.ca.shared.global [%0], [%1], 16, %2;\n"
                 :: "r"(s), "l"(gsrc), "r"(srcbytes));
}
__device__ __forceinline__ void cp_commit() { asm volatile("cp.async.commit_group;\n"); }
__device__ __forceinline__ void cp_wait0()  { asm volatile("cp.async.wait_group 0;\n"); }
__device__ __forceinline__ void cp_wait1()  { asm volatile("cp.async.wait_group 1;\n"); }

// ============================================================================
// Kernel P: blockIdx.x < 16 : transpose+convert x[b][c][p] f32 -> g_xh[b][p][c]
//           blockIdx.x ==16 : convert w1 -> g_w1h (2 rows per blockIdx.y)
// ============================================================================
__global__ void __launch_bounds__(256)
kernelP(const float* __restrict__ x, const float* __restrict__ w1) {
    const int tid = threadIdx.x;
    const int b   = blockIdx.y;

    if (blockIdx.x == 16) {   // w1 convert: rows [2b, 2b+2)
        const int e0 = b * 2048;
        #pragma unroll
        for (int it = 0; it < 2; it++) {
            int idx = it * 256 + tid;
            float4 v = reinterpret_cast<const float4*>(w1 + e0)[idx];
            __half2 h0 = __floats2half2_rn(v.x, v.y);
            __half2 h1 = __floats2half2_rn(v.z, v.w);
            uint2 u;
            u.x = *reinterpret_cast<uint32_t*>(&h0);
            u.y = *reinterpret_cast<uint32_t*>(&h1);
            reinterpret_cast<uint2*>(g_w1h + e0)[idx] = u;
        }
        return;
    }

    __shared__ unsigned short xs[64 * 202];
    const int c0 = blockIdx.x * 64;

    // incremental (c,q): 256 = 5*49 + 11, no per-iter division
    {
        int c = tid / 49, q = tid - c * 49;
        for (int idx = tid; idx < 64 * 49; idx += 256) {
            float4 v = reinterpret_cast<const float4*>(
                           x + ((size_t)b * C_ + c0 + c) * P_)[q];
            unsigned short* dst = xs + c * 202 + q * 4;
            dst[0] = __half_as_ushort(__float2half_rn(v.x));
            dst[1] = __half_as_ushort(__float2half_rn(v.y));
            dst[2] = __half_as_ushort(__float2half_rn(v.z));
            dst[3] = __half_as_ushort(__float2half_rn(v.w));
            c += 5; q += 11;
            if (q >= 49) { q -= 49; c++; }
        }
    }
    __syncthreads();

    // write x_h[b][p][c0..c0+63]: uint4 per thread = 8 consecutive c
    uint4* outu4 = reinterpret_cast<uint4*>(g_xh);
    for (int idx = tid; idx < P_ * 8; idx += 256) {
        int p = idx >> 3, ch = idx & 7;                  // ch = c-octet
        const unsigned short* s0 = xs + (8 * ch) * 202 + p;
        uint4 u;
        u.x = (uint32_t)s0[0 * 202] | ((uint32_t)s0[1 * 202] << 16);
        u.y = (uint32_t)s0[2 * 202] | ((uint32_t)s0[3 * 202] << 16);
        u.z = (uint32_t)s0[4 * 202] | ((uint32_t)s0[5 * 202] << 16);
        u.w = (uint32_t)s0[6 * 202] | ((uint32_t)s0[7 * 202] << 16);
        outu4[((size_t)b * P_ + p) * (C_ / 8) + (c0 >> 3) + ch] = u;
    }
}

// ============================================================================
// Kernel A: GEMM  H[r,p] = sum_c w1[r,c] * x[b,c,p]   (fp16 HMMA m16n8k16)
// fused BN-affine + hardswish + mean over p  ->  g_hmean[b][r]
// CTA = (mhalf, batch): 128 r rows x 196 p (two passes of 112).
// 256 threads = 8 warps (4M x 2N), warp tile 32x56.
// K chunked by 64, 3-stage cp.async, ldmatrix frags (144B pitch, conflict-free).
// ============================================================================
#define KC      64
#define NKC     16     // 1024/64
#define NPW     112    // N (p) columns per pass
#define PITCH   144    // row pitch bytes (36 words: LDSM phases cover all banks)
#define ASZ     18432  // 128 rows * 144 B
#define BSZ     16128  // 112 rows * 144 B

// smem byte offsets
#define OFF_A    0
#define OFF_B    (3 * ASZ)                   // 55296
#define OFF_PART (OFF_B + 3 * BSZ)           // 103680 (512 f32)
#define OFF_SC   (OFF_PART + 2048)           // 105728 (128 f32)
#define OFF_BI   (OFF_SC + 512)              // 106240 (128 f32)
#define SMEM_A_TOTAL (OFF_BI + 512)          // 106752 B

__global__ void __launch_bounds__(256, 2)
kernelA(const float* __restrict__ g1, const float* __restrict__ b1,
        const float* __restrict__ m1, const float* __restrict__ v1) {
    extern __shared__ __align__(16) char smem[];
    float* part = reinterpret_cast<float*>(smem + OFF_PART);
    float* sc   = reinterpret_cast<float*>(smem + OFF_SC);
    float* bi   = reinterpret_cast<float*>(smem + OFF_BI);
    const uint32_t sbase = (uint32_t)__cvta_generic_to_shared(smem);

    const int mh   = blockIdx.x;
    const int b    = blockIdx.y;
    const int tid  = threadIdx.x;
    const int lane = tid & 31;
    const int warp = tid >> 5;
    const int wm   = warp >> 1;
    const int wn   = warp & 1;
    const int rbase = mh * 128;

    part[tid]       = 0.f;
    part[tid + 256] = 0.f;
    if (tid < 128) {
        int r = rbase + tid;
        float s = g1[r] * rsqrtf(v1[r] + EPSV);
        sc[tid] = s;
        bi[tid] = b1[r] - m1[r] * s;
    }

    const __half* w1h = g_w1h;
    const __half* xh  = g_xh + (size_t)b * P_ * C_;

    // ldmatrix lane-static address components
    const uint32_t a_row  = (uint32_t)(wm * 32 + (lane & 15));
    const uint32_t a_coff = (uint32_t)((lane >> 4) << 4);
    const int      m4     = lane >> 3;
    const uint32_t b_row4 = (uint32_t)(wn * 56 + ((m4 >> 1) << 3) + (lane & 7));
    const uint32_t b_coff4= (uint32_t)((m4 & 1) << 4);
    const uint32_t b_row2 = (uint32_t)(wn * 56 + 48 + (lane & 7));
    const uint32_t b_coff2= (uint32_t)(((lane >> 3) & 1) << 4);

    #pragma unroll 1
    for (int np = 0; np < 2; np++) {
        __syncthreads();

        auto stageA = [&](int s, int kc) {
            char* base = smem + OFF_A + s * ASZ;
            #pragma unroll
            for (int it = 0; it < 4; it++) {       // 1024 cp16
                int idx = it * 256 + tid;
                int row = idx >> 3, ch = idx & 7;
                cp16(base + row * PITCH + ch * 16,
                     w1h + (size_t)(rbase + row) * C_ + kc + ch * 8, 16);
            }
        };
        auto stageB = [&](int s, int kc) {
            char* base = smem + OFF_B + s * BSZ;
            #pragma unroll
            for (int it = 0; it < 4; it++) {       // 896 cp16
                int idx = it * 256 + tid;
                if (idx < 896) {
                    int row = idx >> 3, ch = idx & 7;
                    int p = np * NPW + row;
                    int ok = (p < P_);
                    const __half* src = xh + (size_t)(ok ? p : 0) * C_ + kc + ch * 8;
                    cp16(base + row * PITCH + ch * 16, src, ok ? 16 : 0);
                }
            }
        };

        stageA(0, 0);  stageB(0, 0);  cp_commit();
        stageA(1, KC); stageB(1, KC); cp_commit();

        float d[2][7][4];
        #pragma unroll
        for (int mt = 0; mt < 2; mt++)
            #pragma unroll
            for (int nt = 0; nt < 7; nt++)
                #pragma unroll
                for (int j = 0; j < 4; j++) d[mt][nt][j] = 0.f;

        #pragma unroll 1
        for (int kci = 0; kci < NKC; kci++) {
            if (kci + 1 < NKC) cp_wait1(); else cp_wait0();
            __syncthreads();

            if (kci + 2 < NKC) {
                int nb = (kci + 2) % 3;
                stageA(nb, (kci + 2) * KC);
                stageB(nb, (kci + 2) * KC);
                cp_commit();
            }

            const uint32_t abase = sbase + OFF_A + (kci % 3) * ASZ;
            const uint32_t bbase = sbase + OFF_B + (kci % 3) * BSZ;

            #pragma unroll
            for (int kk = 0; kk < 4; kk++) {
                const uint32_t kb = (uint32_t)(kk * 32);

                uint32_t a[2][4];
                #pragma unroll
                for (int mt = 0; mt < 2; mt++)
                    ldsm_x4(a[mt][0], a[mt][1], a[mt][2], a[mt][3],
                            abase + (a_row + mt * 16) * PITCH + kb + a_coff);

                uint32_t bb[7][2];
                #pragma unroll
                for (int ntp = 0; ntp < 3; ntp++)
                    ldsm_x4(bb[2 * ntp][0], bb[2 * ntp][1],
                            bb[2 * ntp + 1][0], bb[2 * ntp + 1][1],
                            bbase + (b_row4 + ntp * 16) * PITCH + kb + b_coff4);
                ldsm_x2(bb[6][0], bb[6][1],
                        bbase + b_row2 * PITCH + kb + b_coff2);

                #pragma unroll
                for (int mt = 0; mt < 2; mt++)
                    #pragma unroll
                    for (int nt = 0; nt < 7; nt++)
                        mma_f16(d[mt][nt][0], d[mt][nt][1], d[mt][nt][2], d[mt][nt][3],
                                a[mt][0], a[mt][1], a[mt][2], a[mt][3],
                                bb[nt][0], bb[nt][1]);
            }
        }

        // epilogue
        const int pbase = np * NPW + wn * 56 + (lane & 3) * 2;
        #pragma unroll
        for (int mt = 0; mt < 2; mt++) {
            const int rl0 = wm * 32 + mt * 16 + (lane >> 2);
            const int rl1 = rl0 + 8;
            const float s0c = sc[rl0], b0c = bi[rl0];
            const float s1c = sc[rl1], b1c = bi[rl1];
            float acc0 = 0.f, acc1 = 0.f;
            #pragma unroll
            for (int nt = 0; nt < 7; nt++) {
                #pragma unroll
                for (int jj = 0; jj < 2; jj++) {
                    int p = pbase + nt * 8 + jj;
                    if (p < P_) {
                        float h0 = d[mt][nt][jj] * s0c + b0c;
                        acc0 += h0 * fminf(fmaxf(h0 + 3.f, 0.f), 6.f) * (1.f / 6.f);
                        float h1 = d[mt][nt][2 + jj] * s1c + b1c;
                        acc1 += h1 * fminf(fmaxf(h1 + 3.f, 0.f), 6.f) * (1.f / 6.f);
                    }
                }
            }
            acc0 += __shfl_xor_sync(0xFFFFFFFFu, acc0, 1);
            acc0 += __shfl_xor_sync(0xFFFFFFFFu, acc0, 2);
            acc1 += __shfl_xor_sync(0xFFFFFFFFu, acc1, 1);
            acc1 += __shfl_xor_sync(0xFFFFFFFFu, acc1, 2);
            if ((lane & 3) == 0) {
                part[(np * 2 + wn) * 128 + rl0] += acc0;
                part[(np * 2 + wn) * 128 + rl1] += acc1;
            }
        }
    }

    __syncthreads();
    if (tid < 128)
        g_hmean[b * R_ + rbase + tid] = (part[tid] + part[128 + tid] +
                                         part[256 + tid] + part[384 + tid]) * (1.f / (float)P_);
}

// ============================================================================
// Kernel C: head (logits/sigmoid/coords, recomputed per block) + ROI align 3D.
// Block = (64-ch tile, batch), 256 thr. cp.async tile staging overlaps
// coords + tap-table computation. fp16 obuf. Packed (w,idx) uint2 tables.
// ============================================================================
__global__ void __launch_bounds__(256)
kernelC(const float* __restrict__ w2, const float* __restrict__ g2,
        const float* __restrict__ b2, const float* __restrict__ m2,
        const float* __restrict__ v2, float* __restrict__ out) {
    __shared__ __half xs[P_ * 64];       // 25088 B
    __shared__ __half obuf[75 * 66];     // 9900 B
    __shared__ uint2  wi[75 * 8];        // 4800 B : {w bits, flat idx}
    __shared__ float  csm[6];

    const int tid  = threadIdx.x;
    const int lane = tid & 31;
    const int warp = tid >> 5;
    const int b    = blockIdx.y;
    const int cc   = blockIdx.x * 64;

    const __half* xh = g_xh + (size_t)b * P_ * C_;

    // async tile stage: 1568 cp16 (overlaps with coords/table computation)
    #pragma unroll
    for (int it = 0; it < 7; it++) {
        int i = it * 256 + tid;
        if (i < P_ * 8) {
            int p = i >> 3, q = i & 7;
            cp16(xs + p * 64 + q * 8, xh + (size_t)p * C_ + cc + q * 8, 16);
        }
    }
    cp_commit();

    // inline head: warp j (<6) computes logit j -> coord csm[j]
    if (warp < 6) {
        const float* h = g_hmean + b * R_;
        float s = 0.f;
        #pragma unroll
        for (int r = lane; r < R_; r += 32) s += h[r] * w2[warp * R_ + r];
        #pragma unroll
        for (int off = 16; off; off >>= 1) s += __shfl_xor_sync(0xFFFFFFFFu, s, off);
        if (lane == 0) {
            float sf = g2[warp] * rsqrtf(v2[warp] + EPSV);
            float l  = (s - m2[warp]) * sf + b2[warp];
            float sig = 1.f / (1.f + expf(-l));
            const float SC[3] = {7.f, 7.f, 4.f};
            csm[warp] = (warp < 3) ? (0.5f * sig * SC[warp])
                                   : ((1.f - 0.5f * sig) * SC[warp - 3]);
        }
    }
    __syncthreads();

    if (tid < 75) {
        const int ot = tid / 25, rr = tid % 25;
        const int oy = rr / 5,   ox = rr - oy * 5;

        auto prep = [&](int axis, int i, int n, float size,
                        int& lo, int& hi, float& w0, float& w1) {
            float s = csm[axis], e = csm[3 + axis];
            float bin = (e - s) / (float)n;
            float c = s + ((float)i + 0.5f) * bin;
            float valid = (c >= -1.f && c <= size) ? 1.f : 0.f;
            c = fminf(fmaxf(c, 0.f), size - 1.f);
            lo = (int)floorf(c);
            hi = min(lo + 1, (int)size - 1);
            float f = c - (float)lo;
            w0 = (1.f - f) * valid;
            w1 = f * valid;
        };

        int xl, xh2, yl, yh2, tl, th2;
        float xw0, xw1, yw0, yw1, tw0, tw1;
        prep(0, ox, 5, 7.f, xl, xh2, xw0, xw1);
        prep(1, oy, 5, 7.f, yl, yh2, yw0, yw1);
        prep(2, ot, 3, 4.f, tl, th2, tw0, tw1);

        #pragma unroll
        for (int k = 0; k < 8; k++) {
            int ti = (k & 4) ? th2 : tl;  float tw = (k & 4) ? tw1 : tw0;
            int yi = (k & 2) ? yh2 : yl;  float yw = (k & 2) ? yw1 : yw0;
            int xi = (k & 1) ? xh2 : xl;  float xw = (k & 1) ? xw1 : xw0;
            uint2 u;
            u.x = __float_as_uint(tw * yw * xw);
            u.y = (uint32_t)(ti * 49 + yi * 7 + xi);
            wi[tid * 8 + k] = u;
        }
    }
    cp_wait0();
    __syncthreads();

    // gather: warp owns o; lane = channel pair. Even/odd taps accumulate
    // into independent registers. Packed LDS.64 for (w, idx).
    #pragma unroll 1
    for (int o = warp; o < 75; o += 8) {
        float ax0 = 0.f, ay0 = 0.f, ax1 = 0.f, ay1 = 0.f;
        #pragma unroll
        for (int k = 0; k < 8; k += 2) {
            uint2 u0 = wi[o * 8 + k];
            uint2 u1 = wi[o * 8 + k + 1];
            float w0 = __uint_as_float(u0.x);
            float w1 = __uint_as_float(u1.x);
            __half2 h0 = *reinterpret_cast<const __half2*>(xs + u0.y * 64 + lane * 2);
            __half2 h1 = *reinterpret_cast<const __half2*>(xs + u1.y * 64 + lane * 2);
            float2 f0 = __half22float2(h0);
            float2 f1 = __half22float2(h1);
            ax0 += w0 * f0.x;  ay0 += w0 * f0.y;
            ax1 += w1 * f1.x;  ay1 += w1 * f1.y;
        }
        __half2 hv = __floats2half2_rn(ax0 + ax1, ay0 + ay1);
        *reinterpret_cast<__half2*>(obuf + o * 66 + lane * 2) = hv;
    }
    __syncthreads();

    // write-out: out index linear in i; (c,o) tracked incrementally (no div)
    {
        float* ob = out + ((size_t)(b * C_) + cc) * 75;
        int c = tid / 75;
        int o = tid - c * 75;
        for (int i = tid; i < 64 * 75; i += 256) {
            ob[i] = __half2float(obuf[o * 66 + c]);
            c += 3; o += 31;
            if (o >= 75) { o -= 75; c++; }
        }
    }
}

// ============================================================================
extern "C" void kernel_launch(void* const* d_in, const int* in_sizes, int n_in,
                              void* d_out, int out_size) {
    const float* x  = (const float*)d_in[0];
    const float* w1 = (const float*)d_in[1];
    const float* g1 = (const float*)d_in[2];
    const float* b1 = (const float*)d_in[3];
    const float* m1 = (const float*)d_in[4];
    const float* v1 = (const float*)d_in[5];
    const float* w2 = (const float*)d_in[6];
    const float* g2 = (const float*)d_in[7];
    const float* b2 = (const float*)d_in[8];
    const float* m2 = (const float*)d_in[9];
    const float* v2 = (const float*)d_in[10];
    float* out = (float*)d_out;

    cudaFuncSetAttribute(kernelA, cudaFuncAttributeMaxDynamicSharedMemorySize,
                         (int)SMEM_A_TOTAL);

    dim3 gridP(17, B_);
    kernelP<<<gridP, 256>>>(x, w1);
    dim3 gridA(2, B_);
    kernelA<<<gridA, 256, SMEM_A_TOTAL>>>(g1, b1, m1, v1);
    dim3 gridC(C_ / 64, B_);
    kernelC<<<gridC, 256>>>(w2, g2, b2, m2, v2, out);
}

// round 16
// speedup vs baseline: 1.0630x; 1.0061x over previous
#include <cuda_runtime.h>
#include <cuda_fp16.h>
#include <cstdint>
#include <math.h>

// Problem constants
#define B_   128
#define C_   1024
#define R_   256
#define T_   4
#define H_   7
#define W_   7
#define P_   196     // T*H*W
#define EPSV 1e-5f

// ---------------- intermediates (device globals; no allocation allowed) ----
__device__ float  g_hmean[B_ * R_];
__device__ __half g_xh[(size_t)B_ * P_ * C_];   // x transposed: [b][p][c] fp16
__device__ __half g_w1h[R_ * C_];               // w1 fp16: [r][c]

// ---------------- helpers ---------------------------------------------------
__device__ __forceinline__ void mma_f16(float& d0, float& d1, float& d2, float& d3,
                                        uint32_t a0, uint32_t a1, uint32_t a2, uint32_t a3,
                                        uint32_t b0, uint32_t b1) {
    asm volatile(
        "mma.sync.aligned.m16n8k16.row.col.f32.f16.f16.f32 "
        "{%0,%1,%2,%3}, {%4,%5,%6,%7}, {%8,%9}, {%0,%1,%2,%3};\n"
        : "+f"(d0), "+f"(d1), "+f"(d2), "+f"(d3)
        : "r"(a0), "r"(a1), "r"(a2), "r"(a3), "r"(b0), "r"(b1));
}

__device__ __forceinline__ void ldsm_x4(uint32_t& r0, uint32_t& r1, uint32_t& r2,
                                        uint32_t& r3, uint32_t addr) {
    asm volatile("ldmatrix.sync.aligned.m8n8.x4.shared.b16 {%0,%1,%2,%3}, [%4];"
                 : "=r"(r0), "=r"(r1), "=r"(r2), "=r"(r3) : "r"(addr));
}
__device__ __forceinline__ void ldsm_x2(uint32_t& r0, uint32_t& r1, uint32_t addr) {
    asm volatile("ldmatrix.sync.aligned.m8n8.x2.shared.b16 {%0,%1}, [%2];"
                 : "=r"(r0), "=r"(r1) : "r"(addr));
}

__device__ __forceinline__ void cp16(void* smem_dst, const void* gsrc, int srcbytes) {
    uint32_t s = (uint32_t)__cvta_generic_to_shared(smem_dst);
    asm volatile("cp.async.ca.shared.global [%0], [%1], 16, %2;\n"
                 :: "r"(s), "l"(gsrc), "r"(srcbytes));
}
__device__ __forceinline__ void cp_commit() { asm volatile("cp.async.commit_group;\n"); }
__device__ __forceinline__ void cp_wait0()  { asm volatile("cp.async.wait_group 0;\n"); }
__device__ __forceinline__ void cp_wait1()  { asm volatile("cp.async.wait_group 1;\n"); }

// ============================================================================
// Kernel P: blockIdx.x < 16 : transpose+convert x[b][c][p] f32 -> g_xh[b][p][c]
//           blockIdx.x ==16 : convert w1 -> g_w1h (2 rows per blockIdx.y)
// ============================================================================
__global__ void __launch_bounds__(256)
kernelP(const float* __restrict__ x, const float* __restrict__ w1) {
    const int tid = threadIdx.x;
    const int b   = blockIdx.y;

    if (blockIdx.x == 16) {   // w1 convert: rows [2b, 2b+2)
        const int e0 = b * 2048;
        #pragma unroll
        for (int it = 0; it < 2; it++) {
            int idx = it * 256 + tid;
            float4 v = reinterpret_cast<const float4*>(w1 + e0)[idx];
            __half2 h0 = __floats2half2_rn(v.x, v.y);
            __half2 h1 = __floats2half2_rn(v.z, v.w);
            uint2 u;
            u.x = *reinterpret_cast<uint32_t*>(&h0);
            u.y = *reinterpret_cast<uint32_t*>(&h1);
            reinterpret_cast<uint2*>(g_w1h + e0)[idx] = u;
        }
        return;
    }

    __shared__ unsigned short xs[64 * 202];
    const int c0 = blockIdx.x * 64;

    // incremental (c,q): 256 = 5*49 + 11, no per-iter division
    {
        int c = tid / 49, q = tid - c * 49;
        for (int idx = tid; idx < 64 * 49; idx += 256) {
            float4 v = reinterpret_cast<const float4*>(
                           x + ((size_t)b * C_ + c0 + c) * P_)[q];
            unsigned short* dst = xs + c * 202 + q * 4;
            dst[0] = __half_as_ushort(__float2half_rn(v.x));
            dst[1] = __half_as_ushort(__float2half_rn(v.y));
            dst[2] = __half_as_ushort(__float2half_rn(v.z));
            dst[3] = __half_as_ushort(__float2half_rn(v.w));
            c += 5; q += 11;
            if (q >= 49) { q -= 49; c++; }
        }
    }
    __syncthreads();

    // write x_h[b][p][c0..c0+63]: process p-PAIRS — 8 LDS.32 cover 2 p x 8 c,
    // emit two uint4 (8 consecutive c each). 196 = 98*2.
    uint4* outu4 = reinterpret_cast<uint4*>(g_xh);
    for (int idx = tid; idx < 98 * 8; idx += 256) {
        int p2 = idx >> 3, ch = idx & 7;                 // ch = c-octet
        int p  = p2 * 2;
        const unsigned short* s0 = xs + (8 * ch) * 202 + p;
        uint32_t r0 = *reinterpret_cast<const uint32_t*>(s0 + 0 * 202);
        uint32_t r1 = *reinterpret_cast<const uint32_t*>(s0 + 1 * 202);
        uint32_t r2 = *reinterpret_cast<const uint32_t*>(s0 + 2 * 202);
        uint32_t r3 = *reinterpret_cast<const uint32_t*>(s0 + 3 * 202);
        uint32_t r4 = *reinterpret_cast<const uint32_t*>(s0 + 4 * 202);
        uint32_t r5 = *reinterpret_cast<const uint32_t*>(s0 + 5 * 202);
        uint32_t r6 = *reinterpret_cast<const uint32_t*>(s0 + 6 * 202);
        uint32_t r7 = *reinterpret_cast<const uint32_t*>(s0 + 7 * 202);
        uint4 u0, u1;
        u0.x = (r0 & 0xFFFFu) | (r1 << 16);
        u0.y = (r2 & 0xFFFFu) | (r3 << 16);
        u0.z = (r4 & 0xFFFFu) | (r5 << 16);
        u0.w = (r6 & 0xFFFFu) | (r7 << 16);
        u1.x = (r0 >> 16) | (r1 & 0xFFFF0000u);
        u1.y = (r2 >> 16) | (r3 & 0xFFFF0000u);
        u1.z = (r4 >> 16) | (r5 & 0xFFFF0000u);
        u1.w = (r6 >> 16) | (r7 & 0xFFFF0000u);
        size_t base = ((size_t)b * P_ + p) * (C_ / 8) + (c0 >> 3) + ch;
        outu4[base]            = u0;
        outu4[base + (C_ / 8)] = u1;
    }
}

// ============================================================================
// Kernel A: GEMM  H[r,p] = sum_c w1[r,c] * x[b,c,p]   (fp16 HMMA m16n8k16)
// fused BN-affine + hardswish + mean over p  ->  g_hmean[b][r]
// CTA = (mhalf, batch): 128 r rows x 196 p (two passes of 112).
// 256 threads = 8 warps (4M x 2N), warp tile 32x56.
// K chunked by 64, 3-stage cp.async, ldmatrix frags (144B pitch, conflict-free).
// ============================================================================
#define KC      64
#define NKC     16     // 1024/64
#define NPW     112    // N (p) columns per pass
#define PITCH   144    // row pitch bytes (36 words: LDSM phases cover all banks)
#define ASZ     18432  // 128 rows * 144 B
#define BSZ     16128  // 112 rows * 144 B

// smem byte offsets
#define OFF_A    0
#define OFF_B    (3 * ASZ)                   // 55296
#define OFF_PART (OFF_B + 3 * BSZ)           // 103680 (512 f32)
#define OFF_SC   (OFF_PART + 2048)           // 105728 (128 f32)
#define OFF_BI   (OFF_SC + 512)              // 106240 (128 f32)
#define SMEM_A_TOTAL (OFF_BI + 512)          // 106752 B

__global__ void __launch_bounds__(256, 2)
kernelA(const float* __restrict__ g1, const float* __restrict__ b1,
        const float* __restrict__ m1, const float* __restrict__ v1) {
    extern __shared__ __align__(16) char smem[];
    float* part = reinterpret_cast<float*>(smem + OFF_PART);
    float* sc   = reinterpret_cast<float*>(smem + OFF_SC);
    float* bi   = reinterpret_cast<float*>(smem + OFF_BI);
    const uint32_t sbase = (uint32_t)__cvta_generic_to_shared(smem);

    const int mh   = blockIdx.x;
    const int b    = blockIdx.y;
    const int tid  = threadIdx.x;
    const int lane = tid & 31;
    const int warp = tid >> 5;
    const int wm   = warp >> 1;
    const int wn   = warp & 1;
    const int rbase = mh * 128;

    part[tid]       = 0.f;
    part[tid + 256] = 0.f;
    if (tid < 128) {
        int r = rbase + tid;
        float s = g1[r] * rsqrtf(v1[r] + EPSV);
        sc[tid] = s;
        bi[tid] = b1[r] - m1[r] * s;
    }

    const __half* w1h = g_w1h;
    const __half* xh  = g_xh + (size_t)b * P_ * C_;

    // ldmatrix lane-static address components
    const uint32_t a_row  = (uint32_t)(wm * 32 + (lane & 15));
    const uint32_t a_coff = (uint32_t)((lane >> 4) << 4);
    const int      m4     = lane >> 3;
    const uint32_t b_row4 = (uint32_t)(wn * 56 + ((m4 >> 1) << 3) + (lane & 7));
    const uint32_t b_coff4= (uint32_t)((m4 & 1) << 4);
    const uint32_t b_row2 = (uint32_t)(wn * 56 + 48 + (lane & 7));
    const uint32_t b_coff2= (uint32_t)(((lane >> 3) & 1) << 4);

    #pragma unroll 1
    for (int np = 0; np < 2; np++) {
        __syncthreads();

        auto stageA = [&](int s, int kc) {
            char* base = smem + OFF_A + s * ASZ;
            #pragma unroll
            for (int it = 0; it < 4; it++) {       // 1024 cp16
                int idx = it * 256 + tid;
                int row = idx >> 3, ch = idx & 7;
                cp16(base + row * PITCH + ch * 16,
                     w1h + (size_t)(rbase + row) * C_ + kc + ch * 8, 16);
            }
        };
        auto stageB = [&](int s, int kc) {
            char* base = smem + OFF_B + s * BSZ;
            #pragma unroll
            for (int it = 0; it < 4; it++) {       // 896 cp16
                int idx = it * 256 + tid;
                if (idx < 896) {
                    int row = idx >> 3, ch = idx & 7;
                    int p = np * NPW + row;
                    int ok = (p < P_);
                    const __half* src = xh + (size_t)(ok ? p : 0) * C_ + kc + ch * 8;
                    cp16(base + row * PITCH + ch * 16, src, ok ? 16 : 0);
                }
            }
        };

        stageA(0, 0);  stageB(0, 0);  cp_commit();
        stageA(1, KC); stageB(1, KC); cp_commit();

        float d[2][7][4];
        #pragma unroll
        for (int mt = 0; mt < 2; mt++)
            #pragma unroll
            for (int nt = 0; nt < 7; nt++)
                #pragma unroll
                for (int j = 0; j < 4; j++) d[mt][nt][j] = 0.f;

        #pragma unroll 1
        for (int kci = 0; kci < NKC; kci++) {
            if (kci + 1 < NKC) cp_wait1(); else cp_wait0();
            __syncthreads();

            if (kci + 2 < NKC) {
                int nb = (kci + 2) % 3;
                stageA(nb, (kci + 2) * KC);
                stageB(nb, (kci + 2) * KC);
                cp_commit();
            }

            const uint32_t abase = sbase + OFF_A + (kci % 3) * ASZ;
            const uint32_t bbase = sbase + OFF_B + (kci % 3) * BSZ;

            #pragma unroll
            for (int kk = 0; kk < 4; kk++) {
                const uint32_t kb = (uint32_t)(kk * 32);

                uint32_t a[2][4];
                #pragma unroll
                for (int mt = 0; mt < 2; mt++)
                    ldsm_x4(a[mt][0], a[mt][1], a[mt][2], a[mt][3],
                            abase + (a_row + mt * 16) * PITCH + kb + a_coff);

                uint32_t bb[7][2];
                #pragma unroll
                for (int ntp = 0; ntp < 3; ntp++)
                    ldsm_x4(bb[2 * ntp][0], bb[2 * ntp][1],
                            bb[2 * ntp + 1][0], bb[2 * ntp + 1][1],
                            bbase + (b_row4 + ntp * 16) * PITCH + kb + b_coff4);
                ldsm_x2(bb[6][0], bb[6][1],
                        bbase + b_row2 * PITCH + kb + b_coff2);

                #pragma unroll
                for (int mt = 0; mt < 2; mt++)
                    #pragma unroll
                    for (int nt = 0; nt < 7; nt++)
                        mma_f16(d[mt][nt][0], d[mt][nt][1], d[mt][nt][2], d[mt][nt][3],
                                a[mt][0], a[mt][1], a[mt][2], a[mt][3],
                                bb[nt][0], bb[nt][1]);
            }
        }

        // epilogue
        const int pbase = np * NPW + wn * 56 + (lane & 3) * 2;
        #pragma unroll
        for (int mt = 0; mt < 2; mt++) {
            const int rl0 = wm * 32 + mt * 16 + (lane >> 2);
            const int rl1 = rl0 + 8;
            const float s0c = sc[rl0], b0c = bi[rl0];
            const float s1c = sc[rl1], b1c = bi[rl1];
            float acc0 = 0.f, acc1 = 0.f;
            #pragma unroll
            for (int nt = 0; nt < 7; nt++) {
                #pragma unroll
                for (int jj = 0; jj < 2; jj++) {
                    int p = pbase + nt * 8 + jj;
                    if (p < P_) {
                        float h0 = d[mt][nt][jj] * s0c + b0c;
                        acc0 += h0 * fminf(fmaxf(h0 + 3.f, 0.f), 6.f) * (1.f / 6.f);
                        float h1 = d[mt][nt][2 + jj] * s1c + b1c;
                        acc1 += h1 * fminf(fmaxf(h1 + 3.f, 0.f), 6.f) * (1.f / 6.f);
                    }
                }
            }
            acc0 += __shfl_xor_sync(0xFFFFFFFFu, acc0, 1);
            acc0 += __shfl_xor_sync(0xFFFFFFFFu, acc0, 2);
            acc1 += __shfl_xor_sync(0xFFFFFFFFu, acc1, 1);
            acc1 += __shfl_xor_sync(0xFFFFFFFFu, acc1, 2);
            if ((lane & 3) == 0) {
                part[(np * 2 + wn) * 128 + rl0] += acc0;
                part[(np * 2 + wn) * 128 + rl1] += acc1;
            }
        }
    }

    __syncthreads();
    if (tid < 128)
        g_hmean[b * R_ + rbase + tid] = (part[tid] + part[128 + tid] +
                                         part[256 + tid] + part[384 + tid]) * (1.f / (float)P_);
}

// ============================================================================
// Kernel C: head (logits/sigmoid/coords, recomputed per block) + ROI align 3D.
// Block = (64-ch tile, batch), 256 thr. cp.async tile staging overlaps
// coords + tap-table computation. fp16 obuf. Packed uint4 tap tables.
// ============================================================================
__global__ void __launch_bounds__(256)
kernelC(const float* __restrict__ w2, const float* __restrict__ g2,
        const float* __restrict__ b2, const float* __restrict__ m2,
        const float* __restrict__ v2, float* __restrict__ out) {
    __shared__ __half xs[P_ * 64];       // 25088 B
    __shared__ __half obuf[75 * 66];     // 9900 B
    __shared__ uint4  wi4[75 * 4];       // 4800 B : {w0,idx0,w1,idx1} per tap-pair
    __shared__ float  csm[6];

    const int tid  = threadIdx.x;
    const int lane = tid & 31;
    const int warp = tid >> 5;
    const int b    = blockIdx.y;
    const int cc   = blockIdx.x * 64;

    const __half* xh = g_xh + (size_t)b * P_ * C_;

    // async tile stage: 1568 cp16 (overlaps with coords/table computation)
    #pragma unroll
    for (int it = 0; it < 7; it++) {
        int i = it * 256 + tid;
        if (i < P_ * 8) {
            int p = i >> 3, q = i & 7;
            cp16(xs + p * 64 + q * 8, xh + (size_t)p * C_ + cc + q * 8, 16);
        }
    }
    cp_commit();

    // inline head: warp j (<6) computes logit j -> coord csm[j]
    if (warp < 6) {
        const float* h = g_hmean + b * R_;
        float s = 0.f;
        #pragma unroll
        for (int r = lane; r < R_; r += 32) s += h[r] * w2[warp * R_ + r];
        #pragma unroll
        for (int off = 16; off; off >>= 1) s += __shfl_xor_sync(0xFFFFFFFFu, s, off);
        if (lane == 0) {
            float sf = g2[warp] * rsqrtf(v2[warp] + EPSV);
            float l  = (s - m2[warp]) * sf + b2[warp];
            float sig = 1.f / (1.f + expf(-l));
            const float SC[3] = {7.f, 7.f, 4.f};
            csm[warp] = (warp < 3) ? (0.5f * sig * SC[warp])
                                   : ((1.f - 0.5f * sig) * SC[warp - 3]);
        }
    }
    __syncthreads();

    if (tid < 75) {
        const int ot = tid / 25, rr = tid % 25;
        const int oy = rr / 5,   ox = rr - oy * 5;

        auto prep = [&](int axis, int i, int n, float size,
                        int& lo, int& hi, float& w0, float& w1) {
            float s = csm[axis], e = csm[3 + axis];
            float bin = (e - s) / (float)n;
            float c = s + ((float)i + 0.5f) * bin;
            float valid = (c >= -1.f && c <= size) ? 1.f : 0.f;
            c = fminf(fmaxf(c, 0.f), size - 1.f);
            lo = (int)floorf(c);
            hi = min(lo + 1, (int)size - 1);
            float f = c - (float)lo;
            w0 = (1.f - f) * valid;
            w1 = f * valid;
        };

        int xl, xh2, yl, yh2, tl, th2;
        float xw0, xw1, yw0, yw1, tw0, tw1;
        prep(0, ox, 5, 7.f, xl, xh2, xw0, xw1);
        prep(1, oy, 5, 7.f, yl, yh2, yw0, yw1);
        prep(2, ot, 3, 4.f, tl, th2, tw0, tw1);

        #pragma unroll
        for (int k2 = 0; k2 < 4; k2++) {
            int k0 = 2 * k2, k1 = 2 * k2 + 1;
            int ti0 = (k0 & 4) ? th2 : tl;  float tw0_ = (k0 & 4) ? tw1 : tw0;
            int yi0 = (k0 & 2) ? yh2 : yl;  float yw0_ = (k0 & 2) ? yw1 : yw0;
            int xi0 = (k0 & 1) ? xh2 : xl;  float xw0_ = (k0 & 1) ? xw1 : xw0;
            int ti1 = (k1 & 4) ? th2 : tl;  float tw1_ = (k1 & 4) ? tw1 : tw0;
            int yi1 = (k1 & 2) ? yh2 : yl;  float yw1_ = (k1 & 2) ? yw1 : yw0;
            int xi1 = (k1 & 1) ? xh2 : xl;  float xw1_ = (k1 & 1) ? xw1 : xw0;
            uint4 u;
            u.x = __float_as_uint(tw0_ * yw0_ * xw0_);
            u.y = (uint32_t)(ti0 * 49 + yi0 * 7 + xi0);
            u.z = __float_as_uint(tw1_ * yw1_ * xw1_);
            u.w = (uint32_t)(ti1 * 49 + yi1 * 7 + xi1);
            wi4[tid * 4 + k2] = u;
        }
    }
    cp_wait0();
    __syncthreads();

    // gather: warp owns o; lane = channel pair. Even/odd taps accumulate
    // into independent registers. Packed LDS.128 for two taps.
    #pragma unroll 1
    for (int o = warp; o < 75; o += 8) {
        float ax0 = 0.f, ay0 = 0.f, ax1 = 0.f, ay1 = 0.f;
        #pragma unroll
        for (int k2 = 0; k2 < 4; k2++) {
            uint4 u = wi4[o * 4 + k2];
            float w0 = __uint_as_float(u.x);
            float w1 = __uint_as_float(u.z);
            __half2 h0 = *reinterpret_cast<const __half2*>(xs + u.y * 64 + lane * 2);
            __half2 h1 = *reinterpret_cast<const __half2*>(xs + u.w * 64 + lane * 2);
            float2 f0 = __half22float2(h0);
            float2 f1 = __half22float2(h1);
            ax0 += w0 * f0.x;  ay0 += w0 * f0.y;
            ax1 += w1 * f1.x;  ay1 += w1 * f1.y;
        }
        __half2 hv = __floats2half2_rn(ax0 + ax1, ay0 + ay1);
        *reinterpret_cast<__half2*>(obuf + o * 66 + lane * 2) = hv;
    }
    __syncthreads();

    // write-out: out index linear in i; (c,o) tracked incrementally (no div)
    {
        float* ob = out + ((size_t)(b * C_) + cc) * 75;
        int c = tid / 75;
        int o = tid - c * 75;
        for (int i = tid; i < 64 * 75; i += 256) {
            ob[i] = __half2float(obuf[o * 66 + c]);
            c += 3; o += 31;
            if (o >= 75) { o -= 75; c++; }
        }
    }
}

// ============================================================================
extern "C" void kernel_launch(void* const* d_in, const int* in_sizes, int n_in,
                              void* d_out, int out_size) {
    const float* x  = (const float*)d_in[0];
    const float* w1 = (const float*)d_in[1];
    const float* g1 = (const float*)d_in[2];
    const float* b1 = (const float*)d_in[3];
    const float* m1 = (const float*)d_in[4];
    const float* v1 = (const float*)d_in[5];
    const float* w2 = (const float*)d_in[6];
    const float* g2 = (const float*)d_in[7];
    const float* b2 = (const float*)d_in[8];
    const float* m2 = (const float*)d_in[9];
    const float* v2 = (const float*)d_in[10];
    float* out = (float*)d_out;

    cudaFuncSetAttribute(kernelA, cudaFuncAttributeMaxDynamicSharedMemorySize,
                         (int)SMEM_A_TOTAL);

    dim3 gridP(17, B_);
    kernelP<<<gridP, 256>>>(x, w1);
    dim3 gridA(2, B_);
    kernelA<<<gridA, 256, SMEM_A_TOTAL>>>(g1, b1, m1, v1);
    dim3 gridC(C_ / 64, B_);
    kernelC<<<gridC, 256>>>(w2, g2, b2, m2, v2, out);
}